// round 13
// baseline (speedup 1.0000x reference)
#include <cuda_runtime.h>

#define L_FIXED 2048
#define TILE    128
#define JT      64
#define NT      16
#define NTP     136
#define MAXB    16
#define EPSF    1e-8f
#define THRC    2.2601f                 // 1.5^2 + dot-form fp32 margin
#define NTHREADS 256

typedef unsigned long long ull;

// ---- global accumulators (zero at load; finalize resets for graph replay) ----
__device__ double   g_clash = 0.0;
__device__ double   g_bn    = 0.0;
__device__ double   g_bd    = 0.0;
__device__ double   g_lin   = 0.0;
__device__ double   g_S[MAXB];
__device__ unsigned g_count = 0;

// ---- Blackwell packed f32x2 helpers ----
__device__ __forceinline__ ull pack2(float x) {
    ull r; asm("mov.b64 %0, {%1, %1};" : "=l"(r) : "f"(x)); return r;
}
__device__ __forceinline__ ull fma2(ull a, ull b, ull c) {
    ull r; asm("fma.rn.f32x2 %0, %1, %2, %3;" : "=l"(r) : "l"(a), "l"(b), "l"(c)); return r;
}
__device__ __forceinline__ void unpack2(ull v, float &lo, float &hi) {
    asm("mov.b64 {%0, %1}, %2;" : "=f"(lo), "=f"(hi) : "l"(v));
}
__device__ __forceinline__ float sqrt_apx(float x) {
    float r; asm("sqrt.approx.f32 %0, %1;" : "=f"(r) : "f"(x)); return r;
}
__device__ __forceinline__ float warp_sum(float v) {
    #pragma unroll
    for (int off = 16; off > 0; off >>= 1)
        v += __shfl_down_sync(0xffffffffu, v, off);
    return v;
}
// bounded lattice displacement: min sep 16, coords <= ~1.21e4
// (dot-form abs error << 16^2 => displaced atoms can never flag a hit)
__device__ __forceinline__ void displace(int i, float &X, float &Y, float &Z) {
    X = 1.0e4f + 16.0f * (float)(i & 127);
    Y = 16.0f * (float)(i >> 7);
    Z = 0.0f;
}

// ============================================================
// grid = (136 tile-pairs, B, 2 j-halves), block = 256.
// 128 i-rows x 64 j-cols per block; 4 i-rows/thread, 8 j/thread.
// Fast loop: pure LDS + FFMA2 + OR (no vote, no branch, no unpack).
// ONE vote per thread afterwards; hit warps re-run the 4 k-iters
// with unpack + sqrt + seq-sep masking.
// ============================================================
__global__ void __launch_bounds__(NTHREADS)
fused_violation_kernel(const float* __restrict__ pos,
                       const float* __restrict__ mask,
                       float* __restrict__ out, int B)
{
    const int p   = blockIdx.x;
    const int b   = blockIdx.y;
    const int zh  = blockIdx.z;
    const int tid = threadIdx.x;

    // closed-form triangular decode (exact at perfect squares)
    const int ti = (int)((33.0f - sqrtf(1089.0f - 8.0f * (float)p)) * 0.5f);
    const int tj = ti + (p - (ti * (33 - ti)) / 2);
    const int i0 = ti * TILE;
    const int j0 = tj * TILE + zh * JT;

    const float* P = pos  + (size_t)b * L_FIXED * 3;
    const float* M = mask + (size_t)b * L_FIXED;

    // ---- stage j sub-tile: x, y, z, q=|r|^2 (packed pairs) ----
    __shared__ ull sjx[JT/2], sjy[JT/2], sjz[JT/2], sjq[JT/2];
    if (tid < JT) {
        int j = j0 + tid;
        float mj = M[j];
        float X = P[3*j], Y = P[3*j+1], Z = P[3*j+2];
        if (mj == 0.0f) displace(j, X, Y, Z);
        ((float*)sjx)[tid] = X;
        ((float*)sjy)[tid] = Y;
        ((float*)sjz)[tid] = Z;
        ((float*)sjq)[tid] = X*X + Y*Y + Z*Z;
    }

    // ---- per-thread i rows (4 consecutive) ----
    const int q = tid & 31;
    const int s = tid >> 5;
    const int ibase = i0 + 4 * q;
    ull x2[4], y2[4], z2[4], c0[4];
    {
        const float4* P4 = (const float4*)(P + 3 * ibase);
        float4 v0 = P4[0], v1 = P4[1], v2 = P4[2];
        float c[12] = {v0.x, v0.y, v0.z, v0.w, v1.x, v1.y, v1.z, v1.w,
                       v2.x, v2.y, v2.z, v2.w};
        const float4 mv = *(const float4*)(M + ibase);
        float mm[4] = {mv.x, mv.y, mv.z, mv.w};
        #pragma unroll
        for (int r = 0; r < 4; r++) {
            int i = ibase + r;
            float X = c[3*r], Y = c[3*r+1], Z = c[3*r+2];
            if (mm[r] == 0.0f) displace(i, X, Y, Z);
            float qq = X*X + Y*Y + Z*Z;
            x2[r] = pack2(-2.0f * X);
            y2[r] = pack2(-2.0f * Y);
            z2[r] = pack2(-2.0f * Z);
            c0[r] = pack2(qq - THRC);
        }
    }
    __syncthreads();

    const ull ONE  = 0x3F8000003F800000ull;
    const ull SMSK = 0x8000000080000000ull;
    const int kb = s * 4;

    // ---- fast scan: branch-free, vote-free ----
    ull hits = 0ull;
    #pragma unroll
    for (int k = 0; k < 4; k++) {
        ull xj = sjx[kb+k], yj = sjy[kb+k], zj = sjz[kb+k], qj = sjq[kb+k];
        ull u0 = fma2(x2[0], xj, fma2(y2[0], yj, fma2(z2[0], zj, fma2(c0[0], ONE, qj))));
        ull u1 = fma2(x2[1], xj, fma2(y2[1], yj, fma2(z2[1], zj, fma2(c0[1], ONE, qj))));
        ull u2 = fma2(x2[2], xj, fma2(y2[2], yj, fma2(z2[2], zj, fma2(c0[2], ONE, qj))));
        ull u3 = fma2(x2[3], xj, fma2(y2[3], yj, fma2(z2[3], zj, fma2(c0[3], ONE, qj))));
        hits |= (u0 | u1) | (u2 | u3);
    }

    // ---- one vote per thread; rare slow path recomputes with sqrt ----
    float acc = 0.0f;
    if (__any_sync(0xffffffffu, (hits & SMSK) != 0ull)) {
        #pragma unroll
        for (int k = 0; k < 4; k++) {
            ull xj = sjx[kb+k], yj = sjy[kb+k], zj = sjz[kb+k], qj = sjq[kb+k];
            int jlo = j0 + 2 * (kb + k), jhi = jlo + 1;
            #pragma unroll
            for (int r = 0; r < 4; r++) {
                int i = ibase + r;
                ull u = fma2(x2[r], xj, fma2(y2[r], yj, fma2(z2[r], zj, fma2(c0[r], ONE, qj))));
                float lo, hi; unpack2(u, lo, hi);
                float dl = fmaxf(lo + THRC, 0.0f) + EPSF;
                float dh = fmaxf(hi + THRC, 0.0f) + EPSF;
                float vl = fmaxf(1.5f - sqrt_apx(dl), 0.0f);
                float vh = fmaxf(1.5f - sqrt_apx(dh), 0.0f);
                if (jlo - i <= 2) vl = 0.0f;   // seq-sep (also kills j<=i)
                if (jhi - i <= 2) vh = 0.0f;
                acc += vl + vh;
            }
        }
    }

    // ---- block reduction of clash partial ----
    __shared__ float swr[NTHREADS / 32];
    acc = warp_sum(acc);
    if ((tid & 31) == 0) swr[tid >> 5] = acc;
    __syncthreads();
    if (tid == 0) {
        float t = 0.0f;
        #pragma unroll
        for (int w = 0; w < NTHREADS / 32; w++) t += swr[w];
        if (t != 0.0f) atomicAdd(&g_clash, (double)t);
    }

    // ---- diagonal stats once per (diagonal tile, batch): zh==0 only ----
    if (ti == tj && zh == 0) {
        float bn = 0.0f, bd = 0.0f, S = 0.0f, lin = 0.0f;
        if (tid < TILE) {
            int i = i0 + tid;
            float m = M[i];
            S = m; lin = m * m;
            if (i + 1 < L_FIXED) {
                float mj = M[i + 1];
                float dx = P[3*(i+1)]   - P[3*i];
                float dy = P[3*(i+1)+1] - P[3*i+1];
                float dz = P[3*(i+1)+2] - P[3*i+2];
                float d  = sqrtf(dx*dx + dy*dy + dz*dz + EPSF);
                float viol = fmaxf(fabsf(d - 3.8f) - 0.4f, 0.0f);
                float mm = m * mj;
                bd = mm; bn = viol * mm; lin += 2.0f * mm;
            }
            if (i + 2 < L_FIXED) lin += 2.0f * m * M[i + 2];
        }
        bn  = warp_sum(bn);
        bd  = warp_sum(bd);
        S   = warp_sum(S);
        lin = warp_sum(lin);
        __shared__ float sst[NTHREADS / 32][4];
        if ((tid & 31) == 0) {
            int w = tid >> 5;
            sst[w][0] = bn; sst[w][1] = bd; sst[w][2] = S; sst[w][3] = lin;
        }
        __syncthreads();
        if (tid == 0) {
            float tbn = 0, tbd = 0, tS = 0, tlin = 0;
            #pragma unroll
            for (int w = 0; w < NTHREADS / 32; w++) {
                tbn += sst[w][0]; tbd += sst[w][1];
                tS  += sst[w][2]; tlin += sst[w][3];
            }
            atomicAdd(&g_bn,  (double)tbn);
            atomicAdd(&g_bd,  (double)tbd);
            atomicAdd(&g_S[b], (double)tS);
            atomicAdd(&g_lin, (double)tlin);
        }
    }

    // ---- last-block finalize ----
    __threadfence();
    __shared__ bool is_last;
    if (tid == 0) {
        unsigned total = gridDim.x * gridDim.y * gridDim.z;
        is_last = (atomicAdd(&g_count, 1u) == total - 1u);
    }
    __syncthreads();
    if (is_last && tid == 0) {
        double pd = 0.0;
        #pragma unroll
        for (int bb = 0; bb < MAXB; bb++) {
            if (bb < B) { double Sb = *((volatile double*)&g_S[bb]); pd += Sb * Sb; }
        }
        pd -= *((volatile double*)&g_lin);
        double bn = *((volatile double*)&g_bn);
        double bd = *((volatile double*)&g_bd);
        double cl = *((volatile double*)&g_clash);
        double bond  = bn / (bd + 1e-8);
        double clash = 2.0 * cl / (pd + 1e-8);
        out[0] = (float)bond;
        out[1] = (float)clash;
        out[2] = (float)(bond + clash);
        g_clash = 0.0; g_bn = 0.0; g_bd = 0.0; g_lin = 0.0; g_count = 0u;
        #pragma unroll
        for (int bb = 0; bb < MAXB; bb++) g_S[bb] = 0.0;
    }
}

extern "C" void kernel_launch(void* const* d_in, const int* in_sizes, int n_in,
                              void* d_out, int out_size)
{
    const float* pos  = (const float*)d_in[0];
    const float* mask = (const float*)d_in[1];
    int B = in_sizes[1] / L_FIXED;
    if (B > MAXB) B = MAXB;

    dim3 grid(NTP, B, 2);
    fused_violation_kernel<<<grid, NTHREADS>>>(pos, mask, (float*)d_out, B);
}

// round 14
// speedup vs baseline: 1.2439x; 1.2439x over previous
#include <cuda_runtime.h>

#define L_FIXED 2048
#define TILE    128
#define JT      64
#define NTP     136
#define MAXB    16
#define EPSF    1e-8f
#define THR2    2.2502f                 // 1.5^2 + fma-chain rounding margin
#define NTHREADS 256

typedef unsigned long long ull;

// ---- global accumulators (zero at load; finalize resets for graph replay) ----
__device__ double   g_clash = 0.0;
__device__ double   g_bn    = 0.0;
__device__ double   g_bd    = 0.0;
__device__ double   g_lin   = 0.0;
__device__ double   g_S[MAXB];
__device__ unsigned g_count = 0;

// ---- Blackwell packed f32x2 helpers ----
__device__ __forceinline__ ull pack2(float x) {
    ull r; asm("mov.b64 %0, {%1, %1};" : "=l"(r) : "f"(x)); return r;
}
__device__ __forceinline__ ull add2(ull a, ull b) {
    ull r; asm("add.rn.f32x2 %0, %1, %2;" : "=l"(r) : "l"(a), "l"(b)); return r;
}
__device__ __forceinline__ ull fma2(ull a, ull b, ull c) {
    ull r; asm("fma.rn.f32x2 %0, %1, %2, %3;" : "=l"(r) : "l"(a), "l"(b), "l"(c)); return r;
}
__device__ __forceinline__ void unpack2(ull v, float &lo, float &hi) {
    asm("mov.b64 {%0, %1}, %2;" : "=f"(lo), "=f"(hi) : "l"(v));
}
__device__ __forceinline__ float sqrt_apx(float x) {
    float r; asm("sqrt.approx.f32 %0, %1;" : "=f"(r) : "f"(x)); return r;
}
__device__ __forceinline__ float warp_sum(float v) {
    #pragma unroll
    for (int off = 16; off > 0; off >>= 1)
        v += __shfl_down_sync(0xffffffffu, v, off);
    return v;
}

// ============================================================
// grid = (136 tile-pairs, B, 2 j-halves), block = 256.
// 128 i-rows x 64 j-cols per block; 4 i-rows/thread, 8 j/thread
// (4 packed k-iters). NO displacement: raw coords in the fast
// path; the vote-gated slow path applies masks + seq-sep exactly.
// Fast path per k: 3 LDS + 4x(3 add2 + 3 fma2) + signOR + vote.
// ============================================================
__global__ void __launch_bounds__(NTHREADS)
fused_violation_kernel(const float* __restrict__ pos,
                       const float* __restrict__ mask,
                       float* __restrict__ out, int B)
{
    const int p   = blockIdx.x;
    const int b   = blockIdx.y;
    const int zh  = blockIdx.z;
    const int tid = threadIdx.x;

    // closed-form triangular decode (exact at perfect squares)
    const int ti = (int)((33.0f - sqrtf(1089.0f - 8.0f * (float)p)) * 0.5f);
    const int tj = ti + (p - (ti * (33 - ti)) / 2);
    const int i0 = ti * TILE;
    const int j0 = tj * TILE + zh * JT;

    const float* P = pos  + (size_t)b * L_FIXED * 3;
    const float* M = mask + (size_t)b * L_FIXED;

    // ---- stage j sub-tile: negated raw coords + mask (packed pairs) ----
    __shared__ ull sjx[JT/2], sjy[JT/2], sjz[JT/2], sjm[JT/2];
    if (tid < JT) {
        int j = j0 + tid;
        ((float*)sjx)[tid] = -P[3*j];
        ((float*)sjy)[tid] = -P[3*j+1];
        ((float*)sjz)[tid] = -P[3*j+2];
        ((float*)sjm)[tid] = M[j];
    }

    // ---- per-thread i rows (4 consecutive): raw coords + masks ----
    const int q = tid & 31;
    const int s = tid >> 5;
    const int ibase = i0 + 4 * q;
    ull xr[4], yr[4], zr[4];
    float mi[4];
    {
        const float4* P4 = (const float4*)(P + 3 * ibase);
        float4 v0 = P4[0], v1 = P4[1], v2 = P4[2];
        xr[0] = pack2(v0.x); yr[0] = pack2(v0.y); zr[0] = pack2(v0.z);
        xr[1] = pack2(v0.w); yr[1] = pack2(v1.x); zr[1] = pack2(v1.y);
        xr[2] = pack2(v1.z); yr[2] = pack2(v1.w); zr[2] = pack2(v2.x);
        xr[3] = pack2(v2.y); yr[3] = pack2(v2.z); zr[3] = pack2(v2.w);
        const float4 mv = *(const float4*)(M + ibase);
        mi[0] = mv.x; mi[1] = mv.y; mi[2] = mv.z; mi[3] = mv.w;
    }
    __syncthreads();

    const ull NEGT = pack2(-THR2);
    const ull SMSK = 0x8000000080000000ull;
    const int kb = s * 4;

    float acc = 0.0f;
    #pragma unroll
    for (int k = 0; k < 4; k++) {
        ull nx = sjx[kb+k], ny = sjy[kb+k], nz = sjz[kb+k];

        ull dx0 = add2(xr[0], nx), dy0 = add2(yr[0], ny), dz0 = add2(zr[0], nz);
        ull u0  = fma2(dz0, dz0, fma2(dy0, dy0, fma2(dx0, dx0, NEGT)));
        ull dx1 = add2(xr[1], nx), dy1 = add2(yr[1], ny), dz1 = add2(zr[1], nz);
        ull u1  = fma2(dz1, dz1, fma2(dy1, dy1, fma2(dx1, dx1, NEGT)));
        ull dx2 = add2(xr[2], nx), dy2 = add2(yr[2], ny), dz2 = add2(zr[2], nz);
        ull u2  = fma2(dz2, dz2, fma2(dy2, dy2, fma2(dx2, dx2, NEGT)));
        ull dx3 = add2(xr[3], nx), dy3 = add2(yr[3], ny), dz3 = add2(zr[3], nz);
        ull u3  = fma2(dz3, dz3, fma2(dy3, dy3, fma2(dx3, dx3, NEGT)));

        ull orv = (u0 | u1) | (u2 | u3);
        if (__any_sync(0xffffffffu, (orv & SMSK) != 0ull)) {
            // exact slow path: masks + seq-sep (rare)
            float ml, mh; unpack2(sjm[kb+k], ml, mh);
            int jlo = j0 + 2 * (kb + k), jhi = jlo + 1;
            ull uu[4] = {u0, u1, u2, u3};
            #pragma unroll
            for (int r = 0; r < 4; r++) {
                int i = ibase + r;
                float lo, hi; unpack2(uu[r], lo, hi);
                float dl = fmaxf(lo + THR2, 0.0f) + EPSF;
                float dh = fmaxf(hi + THR2, 0.0f) + EPSF;
                float vl = fmaxf(1.5f - sqrt_apx(dl), 0.0f);
                float vh = fmaxf(1.5f - sqrt_apx(dh), 0.0f);
                if (jlo - i <= 2) vl = 0.0f;   // seq-sep (also kills j<=i)
                if (jhi - i <= 2) vh = 0.0f;
                acc += mi[r] * (vl * ml + vh * mh);
            }
        }
    }

    // ---- block reduction of clash partial ----
    __shared__ float swr[NTHREADS / 32];
    acc = warp_sum(acc);
    if ((tid & 31) == 0) swr[tid >> 5] = acc;
    __syncthreads();
    if (tid == 0) {
        float t = 0.0f;
        #pragma unroll
        for (int w = 0; w < NTHREADS / 32; w++) t += swr[w];
        if (t != 0.0f) atomicAdd(&g_clash, (double)t);
    }

    // ---- diagonal stats once per (diagonal tile, batch): zh==0 only ----
    if (ti == tj && zh == 0) {
        float bn = 0.0f, bd = 0.0f, S = 0.0f, lin = 0.0f;
        if (tid < TILE) {
            int i = i0 + tid;
            float m = M[i];
            S = m; lin = m * m;
            if (i + 1 < L_FIXED) {
                float mj = M[i + 1];
                float dx = P[3*(i+1)]   - P[3*i];
                float dy = P[3*(i+1)+1] - P[3*i+1];
                float dz = P[3*(i+1)+2] - P[3*i+2];
                float d  = sqrtf(dx*dx + dy*dy + dz*dz + EPSF);
                float viol = fmaxf(fabsf(d - 3.8f) - 0.4f, 0.0f);
                float mm = m * mj;
                bd = mm; bn = viol * mm; lin += 2.0f * mm;
            }
            if (i + 2 < L_FIXED) lin += 2.0f * m * M[i + 2];
        }
        bn  = warp_sum(bn);
        bd  = warp_sum(bd);
        S   = warp_sum(S);
        lin = warp_sum(lin);
        __shared__ float sst[NTHREADS / 32][4];
        if ((tid & 31) == 0) {
            int w = tid >> 5;
            sst[w][0] = bn; sst[w][1] = bd; sst[w][2] = S; sst[w][3] = lin;
        }
        __syncthreads();
        if (tid == 0) {
            float tbn = 0, tbd = 0, tS = 0, tlin = 0;
            #pragma unroll
            for (int w = 0; w < NTHREADS / 32; w++) {
                tbn += sst[w][0]; tbd += sst[w][1];
                tS  += sst[w][2]; tlin += sst[w][3];
            }
            atomicAdd(&g_bn,  (double)tbn);
            atomicAdd(&g_bd,  (double)tbd);
            atomicAdd(&g_S[b], (double)tS);
            atomicAdd(&g_lin, (double)tlin);
        }
    }

    // ---- last-block finalize ----
    __threadfence();
    __shared__ bool is_last;
    if (tid == 0) {
        unsigned total = gridDim.x * gridDim.y * gridDim.z;
        is_last = (atomicAdd(&g_count, 1u) == total - 1u);
    }
    __syncthreads();
    if (is_last && tid == 0) {
        double pd = 0.0;
        #pragma unroll
        for (int bb = 0; bb < MAXB; bb++) {
            if (bb < B) { double Sb = *((volatile double*)&g_S[bb]); pd += Sb * Sb; }
        }
        pd -= *((volatile double*)&g_lin);
        double bn = *((volatile double*)&g_bn);
        double bd = *((volatile double*)&g_bd);
        double cl = *((volatile double*)&g_clash);
        double bond  = bn / (bd + 1e-8);
        double clash = 2.0 * cl / (pd + 1e-8);
        out[0] = (float)bond;
        out[1] = (float)clash;
        out[2] = (float)(bond + clash);
        g_clash = 0.0; g_bn = 0.0; g_bd = 0.0; g_lin = 0.0; g_count = 0u;
        #pragma unroll
        for (int bb = 0; bb < MAXB; bb++) g_S[bb] = 0.0;
    }
}

extern "C" void kernel_launch(void* const* d_in, const int* in_sizes, int n_in,
                              void* d_out, int out_size)
{
    const float* pos  = (const float*)d_in[0];
    const float* mask = (const float*)d_in[1];
    int B = in_sizes[1] / L_FIXED;
    if (B > MAXB) B = MAXB;

    dim3 grid(NTP, B, 2);
    fused_violation_kernel<<<grid, NTHREADS>>>(pos, mask, (float*)d_out, B);
}